// round 7
// baseline (speedup 1.0000x reference)
#include <cuda_runtime.h>
#include <cstdint>

// INT8BertEmbeddings R7:
//  Kernel 1: precompute fused pos+type table in fp32 (3 MB device scratch).
//  Kernel 2: warp-per-token, TWO-PASS, zero barriers.
//   Pass 1 streams the row computing sum/sq only (no e[] kept live),
//   warp-shuffle reduce, pass 2 reloads the same lines (L1 hits),
//   recomputes e, normalizes, streaming-stores.
//   Live registers ~= accumulators + temps -> __launch_bounds__(128,12)
//   (40-reg cap) lifts theoretical occupancy to 48 warps/SM.
//   No __syncthreads anywhere (R6's smem exchange hung the bench).

constexpr int H    = 768;
constexpr int VPR  = H / 4;      // 192 float4/int4 per row
constexpr int TPB  = 128;        // 4 warps
constexpr int NW   = TPB / 32;
constexpr int TOKW = 4;          // tokens per warp
constexpr int TOK_PER_CTA = NW * TOKW;   // 16
constexpr int CH   = VPR / 32;   // 6 chunks per warp per row

constexpr int MAX_T = 2;
constexpr int MAX_S = 512;
__device__ float4 g_pt_tab[MAX_T * MAX_S * VPR];   // 3 MB fused pos+type table

__device__ __forceinline__ void store_streaming(float4* addr, float4 v) {
    asm volatile("st.global.cs.v4.f32 [%0], {%1, %2, %3, %4};"
                 :: "l"(addr), "f"(v.x), "f"(v.y), "f"(v.z), "f"(v.w)
                 : "memory");
}

__global__ __launch_bounds__(VPR) void build_pt_kernel(
    const int4* __restrict__ pos_table, const float* __restrict__ pos_scale,
    const int4* __restrict__ type_table, const float* __restrict__ type_scale,
    int S, int T)
{
    const int row = blockIdx.x;          // 0 .. T*S-1
    const int tt  = row / S;
    const int s   = row % S;
    const int tid = threadIdx.x;
    const float ps = __ldg(pos_scale);
    const float ts = __ldg(type_scale);

    const int4 p = __ldg(&pos_table [(size_t)s  * VPR + tid]);
    const int4 t = __ldg(&type_table[(size_t)tt * VPR + tid]);
    float4 o;
    o.x = (float)p.x * ps + (float)t.x * ts;
    o.y = (float)p.y * ps + (float)t.y * ts;
    o.z = (float)p.z * ps + (float)t.z * ts;
    o.w = (float)p.w * ps + (float)t.w * ts;
    g_pt_tab[(size_t)row * VPR + tid] = o;
}

__global__ __launch_bounds__(TPB, 12) void bert_emb_ln_kernel(
    const int*  __restrict__ input_ids,
    const int*  __restrict__ token_type_ids,
    const int4* __restrict__ word_table,
    const float* __restrict__ word_scale,
    const float4* __restrict__ ln_w,
    const float4* __restrict__ ln_b,
    float4* __restrict__ out,
    int S, int n_tokens)
{
    const int lane = threadIdx.x & 31;
    const int warp = threadIdx.x >> 5;
    const int base = (blockIdx.x * NW + warp) * TOKW;

    const float ws = __ldg(word_scale);

    #pragma unroll
    for (int i = 0; i < TOKW; ++i) {
        const int token = base + i;
        if (token >= n_tokens) return;

        const int wrow = __ldg(&input_ids[token]);
        const int trow = __ldg(&token_type_ids[token]);
        const int s    = token % S;

        const int4*   wp = word_table + (size_t)wrow * VPR;
        const float4* pp = g_pt_tab + ((size_t)trow * S + s) * VPR;

        // Pass 1: sums only, nothing kept live.
        float sum = 0.f, sq = 0.f;
        #pragma unroll
        for (int c = 0; c < CH; ++c) {
            const int col = c * 32 + lane;
            const int4   w = __ldg(&wp[col]);
            const float4 q = pp[col];
            const float ex = (float)w.x * ws + q.x;
            const float ey = (float)w.y * ws + q.y;
            const float ez = (float)w.z * ws + q.z;
            const float ew = (float)w.w * ws + q.w;
            sum += ex + ey + ez + ew;
            sq  += ex * ex + ey * ey + ez * ez + ew * ew;
        }

        #pragma unroll
        for (int off = 16; off > 0; off >>= 1) {
            sum += __shfl_xor_sync(0xFFFFFFFFu, sum, off);
            sq  += __shfl_xor_sync(0xFFFFFFFFu, sq,  off);
        }

        const float inv_h = 1.0f / (float)H;
        const float mean  = sum * inv_h;
        float var = sq * inv_h - mean * mean;
        var = fmaxf(var, 0.0f);

        // The reference's 8-iteration Newton-Raphson sqrt converges to
        // sqrt(var) to full fp32 precision for this data's var range.
        const float std_approx = sqrtf(var);
        const float inv_std = __fdividef(1.0f, std_approx + 1e-12f);

        // Pass 2: reload (L1 hits), recompute e, normalize, store.
        float4* orow = out + (size_t)token * VPR;
        #pragma unroll
        for (int c = 0; c < CH; ++c) {
            const int col = c * 32 + lane;
            const int4   w = __ldg(&wp[col]);
            const float4 q = pp[col];
            const float4 g = __ldg(&ln_w[col]);
            const float4 b = __ldg(&ln_b[col]);
            float4 o;
            o.x = g.x * ((((float)w.x * ws + q.x) - mean) * inv_std) + b.x;
            o.y = g.y * ((((float)w.y * ws + q.y) - mean) * inv_std) + b.y;
            o.z = g.z * ((((float)w.z * ws + q.z) - mean) * inv_std) + b.z;
            o.w = g.w * ((((float)w.w * ws + q.w) - mean) * inv_std) + b.w;
            store_streaming(&orow[col], o);
        }
    }
}

extern "C" void kernel_launch(void* const* d_in, const int* in_sizes, int n_in,
                              void* d_out, int out_size)
{
    const int*   input_ids      = (const int*)  d_in[0];
    const int*   token_type_ids = (const int*)  d_in[1];
    const int*   word_table     = (const int*)  d_in[2];
    const float* word_scale     = (const float*)d_in[3];
    const int*   pos_table      = (const int*)  d_in[4];
    const float* pos_scale      = (const float*)d_in[5];
    const int*   type_table     = (const int*)  d_in[6];
    const float* type_scale     = (const float*)d_in[7];
    const float* ln_w           = (const float*)d_in[8];
    const float* ln_b           = (const float*)d_in[9];

    const int n_tokens = in_sizes[0];       // B*S
    const int S        = in_sizes[4] / H;   // 512
    const int T        = in_sizes[6] / H;   // 2

    build_pt_kernel<<<T * S, VPR>>>(
        (const int4*)pos_table, pos_scale,
        (const int4*)type_table, type_scale, S, T);

    const int grid = (n_tokens + TOK_PER_CTA - 1) / TOK_PER_CTA;
    bert_emb_ln_kernel<<<grid, TPB>>>(
        input_ids, token_type_ids,
        (const int4*)word_table, word_scale,
        (const float4*)ln_w, (const float4*)ln_b,
        (float4*)d_out, S, n_tokens);
}

// round 8
// speedup vs baseline: 1.1864x; 1.1864x over previous
#include <cuda_runtime.h>
#include <cstdint>

// INT8BertEmbeddings R8 = R5 (best: 36.9us) + zero-register-cost L1 prefetch
// of the NEXT token's word row and pos+type row. The next token's ~250-cycle
// L2 gather latency overlaps the current token's shuffle-reduction tail and
// epilogue stores; the real loads then hit L1.
//  Kernel 1: precompute fused pos+type table in fp32 (3 MB device scratch).
//  Kernel 2: warp-per-token, single pass, 24 elems/thread, no barriers.

constexpr int H    = 768;
constexpr int VPR  = H / 4;      // 192 float4/int4 per row
constexpr int TPB  = 128;        // 4 warps
constexpr int NW   = TPB / 32;
constexpr int TOKW = 4;          // tokens per warp
constexpr int TOK_PER_CTA = NW * TOKW;   // 16
constexpr int CH   = VPR / 32;   // 6 chunks per warp per row

constexpr int MAX_T = 2;
constexpr int MAX_S = 512;
__device__ float4 g_pt_tab[MAX_T * MAX_S * VPR];   // 3 MB fused pos+type table

__device__ __forceinline__ void store_streaming(float4* addr, float4 v) {
    asm volatile("st.global.cs.v4.f32 [%0], {%1, %2, %3, %4};"
                 :: "l"(addr), "f"(v.x), "f"(v.y), "f"(v.z), "f"(v.w)
                 : "memory");
}

__device__ __forceinline__ void prefetch_l1(const void* p) {
    asm volatile("prefetch.global.L1 [%0];" :: "l"(p));
}

__global__ __launch_bounds__(VPR) void build_pt_kernel(
    const int4* __restrict__ pos_table, const float* __restrict__ pos_scale,
    const int4* __restrict__ type_table, const float* __restrict__ type_scale,
    int S, int T)
{
    const int row = blockIdx.x;          // 0 .. T*S-1
    const int tt  = row / S;
    const int s   = row % S;
    const int tid = threadIdx.x;
    const float ps = __ldg(pos_scale);
    const float ts = __ldg(type_scale);

    const int4 p = __ldg(&pos_table [(size_t)s  * VPR + tid]);
    const int4 t = __ldg(&type_table[(size_t)tt * VPR + tid]);
    float4 o;
    o.x = (float)p.x * ps + (float)t.x * ts;
    o.y = (float)p.y * ps + (float)t.y * ts;
    o.z = (float)p.z * ps + (float)t.z * ts;
    o.w = (float)p.w * ps + (float)t.w * ts;
    g_pt_tab[(size_t)row * VPR + tid] = o;
}

__global__ __launch_bounds__(TPB, 8) void bert_emb_ln_kernel(
    const int*  __restrict__ input_ids,
    const int*  __restrict__ token_type_ids,
    const int4* __restrict__ word_table,
    const float* __restrict__ word_scale,
    const float4* __restrict__ ln_w,
    const float4* __restrict__ ln_b,
    float4* __restrict__ out,
    int S, int n_tokens)
{
    const int lane = threadIdx.x & 31;
    const int warp = threadIdx.x >> 5;
    const int base = (blockIdx.x * NW + warp) * TOKW;

    const float ws = __ldg(word_scale);

    #pragma unroll
    for (int i = 0; i < TOKW; ++i) {
        const int token = base + i;
        if (token >= n_tokens) return;

        // Prefetch next token's rows into L1 (no destination registers):
        // overlaps this token's reduction + epilogue with next token's
        // L2/DRAM gather latency.
        if (i + 1 < TOKW && token + 1 < n_tokens) {
            const int wrow_n = __ldg(&input_ids[token + 1]);
            const int trow_n = __ldg(&token_type_ids[token + 1]);
            const int s_n    = (token + 1) % S;
            const int4*   wpn = word_table + (size_t)wrow_n * VPR;
            const float4* ppn = g_pt_tab + ((size_t)trow_n * S + s_n) * VPR;
            #pragma unroll
            for (int c = 0; c < CH; ++c) {
                const int col = c * 32 + lane;
                prefetch_l1(&wpn[col]);
                prefetch_l1(&ppn[col]);
            }
        }

        const int wrow = __ldg(&input_ids[token]);
        const int trow = __ldg(&token_type_ids[token]);
        const int s    = token % S;

        const int4*   wp = word_table + (size_t)wrow * VPR;
        const float4* pp = g_pt_tab + ((size_t)trow * S + s) * VPR;

        float4 e[CH];
        float sum = 0.f, sq = 0.f;
        #pragma unroll
        for (int c = 0; c < CH; ++c) {
            const int col = c * 32 + lane;
            const int4   w = __ldg(&wp[col]);
            const float4 q = pp[col];
            e[c].x = (float)w.x * ws + q.x;
            e[c].y = (float)w.y * ws + q.y;
            e[c].z = (float)w.z * ws + q.z;
            e[c].w = (float)w.w * ws + q.w;
            sum += e[c].x + e[c].y + e[c].z + e[c].w;
            sq  += e[c].x * e[c].x + e[c].y * e[c].y
                 + e[c].z * e[c].z + e[c].w * e[c].w;
        }

        // Pure warp reduction (full row lives in this warp).
        #pragma unroll
        for (int off = 16; off > 0; off >>= 1) {
            sum += __shfl_xor_sync(0xFFFFFFFFu, sum, off);
            sq  += __shfl_xor_sync(0xFFFFFFFFu, sq,  off);
        }

        const float inv_h = 1.0f / (float)H;
        const float mean  = sum * inv_h;
        float var = sq * inv_h - mean * mean;
        var = fmaxf(var, 0.0f);

        // The reference's 8-iteration Newton-Raphson sqrt converges to
        // sqrt(var) to full fp32 precision for this data's var range.
        const float std_approx = sqrtf(var);
        const float inv_std = __fdividef(1.0f, std_approx + 1e-12f);

        float4* orow = out + (size_t)token * VPR;
        #pragma unroll
        for (int c = 0; c < CH; ++c) {
            const int col = c * 32 + lane;
            const float4 g = __ldg(&ln_w[col]);
            const float4 b = __ldg(&ln_b[col]);
            float4 o;
            o.x = g.x * ((e[c].x - mean) * inv_std) + b.x;
            o.y = g.y * ((e[c].y - mean) * inv_std) + b.y;
            o.z = g.z * ((e[c].z - mean) * inv_std) + b.z;
            o.w = g.w * ((e[c].w - mean) * inv_std) + b.w;
            store_streaming(&orow[col], o);
        }
    }
}

extern "C" void kernel_launch(void* const* d_in, const int* in_sizes, int n_in,
                              void* d_out, int out_size)
{
    const int*   input_ids      = (const int*)  d_in[0];
    const int*   token_type_ids = (const int*)  d_in[1];
    const int*   word_table     = (const int*)  d_in[2];
    const float* word_scale     = (const float*)d_in[3];
    const int*   pos_table      = (const int*)  d_in[4];
    const float* pos_scale      = (const float*)d_in[5];
    const int*   type_table     = (const int*)  d_in[6];
    const float* type_scale     = (const float*)d_in[7];
    const float* ln_w           = (const float*)d_in[8];
    const float* ln_b           = (const float*)d_in[9];

    const int n_tokens = in_sizes[0];       // B*S
    const int S        = in_sizes[4] / H;   // 512
    const int T        = in_sizes[6] / H;   // 2

    build_pt_kernel<<<T * S, VPR>>>(
        (const int4*)pos_table, pos_scale,
        (const int4*)type_table, type_scale, S, T);

    const int grid = (n_tokens + TOK_PER_CTA - 1) / TOK_PER_CTA;
    bert_emb_ln_kernel<<<grid, TPB>>>(
        input_ids, token_type_ids,
        (const int4*)word_table, word_scale,
        (const float4*)ln_w, (const float4*)ln_b,
        (float4*)d_out, S, n_tokens);
}